// round 17
// baseline (speedup 1.0000x reference)
#include <cuda_runtime.h>
#include <cuda_bf16.h>
#include <math.h>
#include <stdint.h>

#define BATCH 4
#define SEQ   4096
#define DIM   1024
#define KSEL  2048
#define NH    16
#define DH    64
#define DFF   4096
#define MTOT  (BATCH*KSEL)

// ---------------- device scratch (no allocs allowed) ----------------
__device__ float          g_logits[BATCH*SEQ];
__device__ int            g_sel[MTOT];
__device__ float          g_rw[MTOT];
__device__ __nv_bfloat16  g_fx[(size_t)MTOT*DIM];
__device__ __nv_bfloat16  g_x2[(size_t)MTOT*DIM];
__device__ __nv_bfloat16  g_h[(size_t)MTOT*DIM];
__device__ __nv_bfloat16  g_q[(size_t)BATCH*NH*KSEL*DH];
__device__ __nv_bfloat16  g_kk[(size_t)BATCH*NH*KSEL*DH];
__device__ __nv_bfloat16  g_vT[(size_t)BATCH*NH*DH*KSEL];
__device__ __nv_bfloat16  g_o[(size_t)MTOT*DIM];
__device__ __nv_bfloat16  g_u[(size_t)MTOT*DFF];
__device__ __nv_bfloat16  g_wqkvT[(size_t)3*DIM*DIM];
__device__ __nv_bfloat16  g_woT[(size_t)DIM*DIM];
__device__ __nv_bfloat16  g_w1T[(size_t)DFF*DIM];
__device__ __nv_bfloat16  g_w2T[(size_t)DIM*DFF];

// ---------------- helpers ----------------
__device__ __forceinline__ uint32_t smem_u32(const void* p){
  return (uint32_t)__cvta_generic_to_shared(p);
}
__device__ __forceinline__ void ldsm4(uint32_t&r0,uint32_t&r1,uint32_t&r2,uint32_t&r3,uint32_t a){
  asm volatile("ldmatrix.sync.aligned.m8n8.x4.shared.b16 {%0,%1,%2,%3},[%4];\n"
    :"=r"(r0),"=r"(r1),"=r"(r2),"=r"(r3):"r"(a));
}
__device__ __forceinline__ void cpa16(uint32_t s, const void* g){
  asm volatile("cp.async.cg.shared.global [%0],[%1],16;\n"::"r"(s),"l"(g));
}
__device__ __forceinline__ void cpcommit(){ asm volatile("cp.async.commit_group;\n"); }
template<int N> __device__ __forceinline__ void cpwait(){
  asm volatile("cp.async.wait_group %0;\n"::"n"(N));
}
__device__ __forceinline__ void mma16816(float* c, const uint32_t* a, const uint32_t* b){
  asm volatile(
    "mma.sync.aligned.m16n8k16.row.col.f32.bf16.bf16.f32 "
    "{%0,%1,%2,%3}, {%4,%5,%6,%7}, {%8,%9}, {%0,%1,%2,%3};\n"
    : "+f"(c[0]),"+f"(c[1]),"+f"(c[2]),"+f"(c[3])
    : "r"(a[0]),"r"(a[1]),"r"(a[2]),"r"(a[3]),"r"(b[0]),"r"(b[1]));
}
__device__ __forceinline__ float gelu_f(float v){
  return 0.5f*v*(1.f + tanhf(0.7978845608028654f*(v + 0.044715f*v*v*v)));
}
__device__ __forceinline__ unsigned long long make_key(float f, int i){
  unsigned u = __float_as_uint(f);
  u = (u & 0x80000000u) ? ~u : (u | 0x80000000u);
  return ((unsigned long long)u << 32) | (unsigned)(0xFFFFFFFFu - (unsigned)i);
}
__device__ __forceinline__ uint32_t packbf2(float a, float b){
  __nv_bfloat162 t = __floats2bfloat162_rn(a, b);
  return *(uint32_t*)&t;
}
__device__ __forceinline__ float2 unpk(uint32_t u){
  __nv_bfloat162 h = *(__nv_bfloat162*)&u;
  return make_float2(__bfloat162float(h.x), __bfloat162float(h.y));
}
// bf16x2 2^x : one MUFU op yields two bf16 results, already packed for mma
__device__ __forceinline__ uint32_t ex2_bf2(uint32_t a){
  uint32_t r;
  asm("ex2.approx.ftz.bf16x2 %0, %1;" : "=r"(r) : "r"(a));
  return r;
}

// ---------------- all weight transposes fp32[K][N] -> bf16[N][K], one launch --
__global__ void __launch_bounds__(256) transpose_all(
    const float* __restrict__ wqkv, const float* __restrict__ wo,
    const float* __restrict__ w1,   const float* __restrict__ w2){
  __shared__ float tile[32][33];
  int bid = blockIdx.x;
  const float* src; __nv_bfloat16* dst; int K, N, n0, k0;
  if (bid < 3072){       src=wqkv; dst=g_wqkvT; K=1024; N=3072; n0=(bid%96)*32;  k0=(bid/96)*32; }
  else if (bid < 4096){  int b=bid-3072; src=wo; dst=g_woT; K=1024; N=1024; n0=(b%32)*32;  k0=(b/32)*32; }
  else if (bid < 8192){  int b=bid-4096; src=w1; dst=g_w1T; K=1024; N=4096; n0=(b%128)*32; k0=(b/128)*32; }
  else {                 int b=bid-8192; src=w2; dst=g_w2T; K=4096; N=1024; n0=(b%32)*32;  k0=(b/32)*32; }
  int tx = threadIdx.x, ty = threadIdx.y;
  #pragma unroll
  for (int i=0;i<4;++i) tile[ty+i*8][tx] = src[(size_t)(k0+ty+i*8)*N + n0 + tx];
  __syncthreads();
  #pragma unroll
  for (int i=0;i<4;++i) dst[(size_t)(n0+ty+i*8)*K + k0 + tx] = __float2bfloat16(tile[tx][ty+i*8]);
}

// ---------------- router logits ----------------
__global__ void logits_kernel(const float* __restrict__ x, const float* __restrict__ rw){
  int warp = threadIdx.x>>5, lane = threadIdx.x&31;
  int row = blockIdx.x*8 + warp;
  const float4* xr = (const float4*)(x + (size_t)row*DIM);
  const float4* wr = (const float4*)rw;
  float s = 0.f;
  for (int i=lane;i<DIM/4;i+=32){
    float4 a = xr[i], w = wr[i];
    s += a.x*w.x + a.y*w.y + a.z*w.z + a.w*w.w;
  }
  #pragma unroll
  for (int o=16;o>0;o>>=1) s += __shfl_xor_sync(0xffffffffu, s, o);
  if (lane==0) g_logits[row] = s;
}

// ---------------- exact top-K + softmax weights + ascending compaction --------
__global__ void __launch_bounds__(1024) topk_kernel(){
  __shared__ unsigned long long keys[SEQ];
  __shared__ float red[1024];
  __shared__ int cnts[1024];
  int b = blockIdx.x, t = threadIdx.x;
  const float* lg = g_logits + b*SEQ;
  for (int i=t;i<SEQ;i+=1024) keys[i] = make_key(lg[i], i);
  __syncthreads();
  for (int k=2;k<=SEQ;k<<=1){
    for (int j=k>>1;j>0;j>>=1){
      for (int i=t;i<SEQ;i+=1024){
        int ixj = i^j;
        if (ixj > i){
          unsigned long long a = keys[i], c = keys[ixj];
          bool up = ((i & k) == 0);
          if (up ? (a < c) : (a > c)){ keys[i]=c; keys[ixj]=a; }
        }
      }
      __syncthreads();
    }
  }
  unsigned long long kth = keys[KSEL-1];
  __syncthreads();
  float lv[4]; bool fl[4]; int cnt=0; float pmax=-1e30f;
  #pragma unroll
  for (int c=0;c<4;++c){
    int i = t*4 + c;
    lv[c] = lg[i];
    fl[c] = (make_key(lv[c], i) >= kth);
    if (fl[c]){ cnt++; pmax = fmaxf(pmax, lv[c]); }
  }
  red[t] = pmax; __syncthreads();
  for (int s=512;s>0;s>>=1){ if (t<s) red[t]=fmaxf(red[t],red[t+s]); __syncthreads(); }
  float mx = red[0]; __syncthreads();
  float psum = 0.f;
  #pragma unroll
  for (int c=0;c<4;++c) if (fl[c]) psum += expf(lv[c]-mx);
  red[t] = psum; __syncthreads();
  for (int s=512;s>0;s>>=1){ if (t<s) red[t]+=red[t+s]; __syncthreads(); }
  float inv = 1.f/red[0];
  cnts[t] = cnt; __syncthreads();
  for (int off=1; off<1024; off<<=1){
    int v = (t>=off) ? cnts[t-off] : 0;
    __syncthreads();
    cnts[t] += v;
    __syncthreads();
  }
  int pos = cnts[t] - cnt;
  #pragma unroll
  for (int c=0;c<4;++c){
    if (fl[c]){
      g_sel[b*KSEL+pos] = t*4+c;
      g_rw[b*KSEL+pos]  = expf(lv[c]-mx)*inv;
      pos++;
    }
  }
}

// ---------------- gather + layernorm (mode0: x->fx,h ; mode1: x2->h) ----------
__global__ void __launch_bounds__(256) ln_kernel(const float* __restrict__ x,
                                                 const float* __restrict__ gma,
                                                 const float* __restrict__ bta,
                                                 int mode){
  int m = blockIdx.x, t = threadIdx.x;
  float4 v;
  if (mode==0){
    int b = m >> 11;
    const float* src = x + (size_t)(b*SEQ + g_sel[m])*DIM;
    v = ((const float4*)src)[t];
    ((uint2*)(g_fx + (size_t)m*DIM))[t] = make_uint2(packbf2(v.x,v.y), packbf2(v.z,v.w));
  } else {
    uint2 raw = ((const uint2*)(g_x2 + (size_t)m*DIM))[t];
    float2 a = unpk(raw.x), b2 = unpk(raw.y);
    v = make_float4(a.x, a.y, b2.x, b2.y);
  }
  float s = v.x+v.y+v.z+v.w;
  float q = v.x*v.x+v.y*v.y+v.z*v.z+v.w*v.w;
  int lane = t&31, warp = t>>5;
  #pragma unroll
  for (int o=16;o>0;o>>=1){ s += __shfl_xor_sync(0xffffffffu,s,o); q += __shfl_xor_sync(0xffffffffu,q,o); }
  __shared__ float rs[8], rq[8];
  if (lane==0){ rs[warp]=s; rq[warp]=q; }
  __syncthreads();
  float S=0.f,Q=0.f;
  #pragma unroll
  for (int i=0;i<8;++i){ S+=rs[i]; Q+=rq[i]; }
  float mean = S*(1.f/DIM);
  float var = Q*(1.f/DIM) - mean*mean;
  float r = rsqrtf(var + 1e-5f);
  float4 gv = ((const float4*)gma)[t];
  float4 bv = ((const float4*)bta)[t];
  float o0 = (v.x-mean)*r*gv.x + bv.x;
  float o1 = (v.y-mean)*r*gv.y + bv.y;
  float o2 = (v.z-mean)*r*gv.z + bv.z;
  float o3 = (v.w-mean)*r*gv.w + bv.w;
  uint32_t* dst = (uint32_t*)(g_h + (size_t)m*DIM + t*4);
  dst[0] = packbf2(o0,o1);
  dst[1] = packbf2(o2,o3);
}

// ---------------- GEMM: C[M,N] = A[M,K] @ B[N,K]^T ----------------
#define GBM 128
#define GBN 128
#define GBK 64
#define NST 3
#define GROW 72
#define TILE_ELEMS (128*GROW)
#define STAGE_BYTES (2*TILE_ELEMS*2)
#define GSMEM_TOTAL (NST*STAGE_BYTES)     // 110592
#define VPITCH 136

template<int EPI>
__global__ void __launch_bounds__(256) gemm_kernel(float* __restrict__ out){
  constexpr int K = (EPI==3)?4096:1024;
  constexpr int N = (EPI==0)?3072:(EPI==2)?4096:1024;
  constexpr int KT = K/GBK;
  const __nv_bfloat16* A = (EPI==0||EPI==2)? g_h : (EPI==1)? g_o : g_u;
  const __nv_bfloat16* B = (EPI==0)? g_wqkvT : (EPI==1)? g_woT : (EPI==2)? g_w1T : g_w2T;
  extern __shared__ __nv_bfloat16 sm[];
  int tid = threadIdx.x;
  int m0 = blockIdx.y*GBM, n0 = blockIdx.x*GBN;
  int w = tid>>5, lane = tid&31;
  int wm = w>>1, wn = w&1;
  float acc[2][8][4] = {};

  auto loadtile = [&](int kt){
    int buf = kt % NST;
    __nv_bfloat16* sa = sm + buf*(2*TILE_ELEMS);
    __nv_bfloat16* sb = sa + TILE_ELEMS;
    int k0 = kt*GBK;
    const __nv_bfloat16* Ag = A + (size_t)m0*K + k0;
    const __nv_bfloat16* Bg = B + (size_t)n0*K + k0;
    #pragma unroll
    for (int t2=0;t2<4;++t2){
      int c = t2*256 + tid; int r = c>>3, o = (c&7)*8;
      cpa16(smem_u32(sa + r*GROW + o), Ag + (size_t)r*K + o);
      cpa16(smem_u32(sb + r*GROW + o), Bg + (size_t)r*K + o);
    }
    cpcommit();
  };

  loadtile(0); loadtile(1);
  for (int kt=0; kt<KT; ++kt){
    if (kt+1 < KT) cpwait<1>(); else cpwait<0>();
    __syncthreads();
    if (kt+2 < KT) loadtile(kt+2);
    int buf = kt % NST;
    const __nv_bfloat16* As = sm + buf*(2*TILE_ELEMS);
    const __nv_bfloat16* Bs = As + TILE_ELEMS;
    #pragma unroll
    for (int ks=0; ks<4; ++ks){
      uint32_t af[2][4];
      #pragma unroll
      for (int mf=0; mf<2; ++mf){
        const __nv_bfloat16* p = &As[(wm*32+mf*16+(lane&15))*GROW + ks*16 + ((lane>>4)<<3)];
        ldsm4(af[mf][0],af[mf][1],af[mf][2],af[mf][3], smem_u32(p));
      }
      #pragma unroll
      for (int nj=0; nj<4; ++nj){
        uint32_t bf[4];
        const __nv_bfloat16* p = &Bs[(wn*64 + nj*16 + ((lane>>4)<<3) + (lane&7))*GROW
                                     + ks*16 + (((lane>>3)&1)<<3)];
        ldsm4(bf[0],bf[1],bf[2],bf[3], smem_u32(p));
        #pragma unroll
        for (int mf=0; mf<2; ++mf){
          mma16816(acc[mf][2*nj],   af[mf], &bf[0]);
          mma16816(acc[mf][2*nj+1], af[mf], &bf[2]);
        }
      }
    }
  }

  const bool isV = (EPI==0) && (n0 >= 2*DIM);
  if (isV) __syncthreads();   // about to reuse pipeline smem as V staging

  int rowbase = m0 + wm*32, colbase = n0 + wn*64;
  #pragma unroll
  for (int mf=0; mf<2; ++mf){
    #pragma unroll
    for (int h2=0; h2<2; ++h2){
      int row = rowbase + mf*16 + (lane>>2) + h2*8;
      #pragma unroll
      for (int nf=0; nf<8; ++nf){
        int col = colbase + nf*8 + (lane&3)*2;
        float v0 = acc[mf][nf][h2*2], v1 = acc[mf][nf][h2*2+1];
        if (EPI==0){
          if (!isV){
            int b = row>>11, rb = row&2047;
            int part = col>>10; int cw = col&1023; int hh = cw>>6; int d = cw&63;
            size_t bh = (size_t)(b*NH+hh);
            __nv_bfloat16* dst = (part==0)? g_q : g_kk;
            *(uint32_t*)&dst[(bh*KSEL+rb)*DH + d] = packbf2(v0,v1);
          } else {
            int cw = col & 1023;
            int hs = (cw>>6) - ((n0&1023)>>6);
            int d = cw&63;
            int sl = row - m0;
            sm[(hs*64+d)*VPITCH + sl]   = __float2bfloat16(v0);
            sm[(hs*64+d+1)*VPITCH + sl] = __float2bfloat16(v1);
          }
        } else if (EPI==1){
          size_t o = (size_t)row*DIM + col;
          float2 f = unpk(*(uint32_t*)&g_fx[o]);
          *(uint32_t*)&g_x2[o] = packbf2(f.x + v0, f.y + v1);
        } else if (EPI==2){
          size_t o = (size_t)row*DFF + col;
          *(uint32_t*)&g_u[o] = packbf2(gelu_f(v0), gelu_f(v1));
        } else {
          int b = row>>11;
          float rw = g_rw[row];
          size_t xo = (size_t)row*DIM + col;
          size_t oo = (size_t)(b*SEQ + g_sel[row])*DIM + col;
          float2 xv = unpk(*(uint32_t*)&g_x2[xo]);
          out[oo]   += rw*(xv.x + v0);
          out[oo+1] += rw*(xv.y + v1);
        }
      }
    }
  }
  if (isV){
    __syncthreads();
    int b = m0>>11, m0rb = m0&2047;
    int hbase = (n0&1023)>>6;
    int r = tid>>1, half = tid&1;
    int hh = hbase + (r>>6), d = r&63;
    const uint4* srcp = (const uint4*)(sm + r*VPITCH + half*64);
    uint4* dstp = (uint4*)(g_vT + ((size_t)(b*NH+hh)*DH + d)*KSEL + m0rb + half*64);
    #pragma unroll
    for (int q=0;q<8;++q) dstp[q] = srcp[q];
  }
}

// ---------------- flash attention: fixed-shift bf16x2 softmax ----------------
// p = exp2(S_raw*C1 - C2): C1 = 0.125*log2(e), C2 = 8*log2(e). Shift cancels in O/l.
#define AC1 0.18033688f
#define AC2 11.5415605f
#define AQ_ELEMS (128*72)
#define AKV_ELEMS (64*72)
#define ASMEM_TOTAL ((AQ_ELEMS + 6*AKV_ELEMS)*2)   // 73728 bytes

__global__ void __launch_bounds__(256) attn_kernel(){
  extern __shared__ __nv_bfloat16 asmem[];
  __nv_bfloat16* Qs = asmem;                       // [128][72]
  __nv_bfloat16* Ks0 = asmem + AQ_ELEMS;           // 3 bufs [64][72]
  __nv_bfloat16* Vs0 = Ks0 + 3*AKV_ELEMS;
  int qt = blockIdx.x, bh = blockIdx.y;
  int w = threadIdx.x>>5, lane = threadIdx.x&31;
  const __nv_bfloat16* Qg = g_q  + (size_t)bh*KSEL*DH + (size_t)qt*128*DH;
  const __nv_bfloat16* Kg = g_kk + (size_t)bh*KSEL*DH;
  const __nv_bfloat16* Vg = g_vT + (size_t)bh*DH*KSEL;
  #pragma unroll
  for (int i=0;i<4;++i){
    int c = threadIdx.x + i*256; int r=c>>3, cc=(c&7)*8;
    cpa16(smem_u32(&Qs[r*72+cc]), Qg + r*DH + cc);
  }
  cpcommit();
  auto loadKV = [&](int kt){
    int buf = kt % 3;
    const __nv_bfloat16* K0 = Kg + (size_t)kt*64*DH;
    const __nv_bfloat16* V0 = Vg + kt*64;
    __nv_bfloat16* Ks = Ks0 + buf*AKV_ELEMS;
    __nv_bfloat16* Vs = Vs0 + buf*AKV_ELEMS;
    #pragma unroll
    for (int i=0;i<2;++i){
      int c = threadIdx.x + i*256; int r=c>>3, cc=(c&7)*8;
      cpa16(smem_u32(&Ks[r*72+cc]), K0 + r*DH + cc);
      cpa16(smem_u32(&Vs[r*72+cc]), V0 + (size_t)r*KSEL + cc);
    }
    cpcommit();
  };
  loadKV(0); loadKV(1);
  uint32_t qa[4][4];
  float l0r=0.f, l1r=0.f;
  float O[8][4] = {};
  for (int kt=0; kt<KSEL/64; ++kt){
    if (kt+1 < KSEL/64) cpwait<1>(); else cpwait<0>();
    __syncthreads();
    if (kt+2 < KSEL/64) loadKV(kt+2);
    if (kt==0){
      #pragma unroll
      for (int ks=0;ks<4;++ks){
        const __nv_bfloat16* p = &Qs[(w*16+(lane&15))*72 + ks*16 + ((lane>>4)<<3)];
        ldsm4(qa[ks][0],qa[ks][1],qa[ks][2],qa[ks][3], smem_u32(p));
      }
    }
    int buf = kt % 3;
    const __nv_bfloat16* Ks = Ks0 + buf*AKV_ELEMS;
    const __nv_bfloat16* Vs = Vs0 + buf*AKV_ELEMS;
    float S[8][4] = {};
    #pragma unroll
    for (int ks=0; ks<4; ++ks){
      #pragma unroll
      for (int nj=0; nj<4; ++nj){
        uint32_t bf[4];
        const __nv_bfloat16* p = &Ks[(nj*16 + ((lane>>4)<<3) + (lane&7))*72
                                     + ks*16 + (((lane>>3)&1)<<3)];
        ldsm4(bf[0],bf[1],bf[2],bf[3], smem_u32(p));
        mma16816(S[2*nj],   qa[ks], &bf[0]);
        mma16816(S[2*nj+1], qa[ks], &bf[2]);
      }
    }
    uint32_t P[8][2];
    #pragma unroll
    for (int nf=0;nf<8;++nf){
      uint32_t a0 = packbf2(fmaf(S[nf][0], AC1, -AC2), fmaf(S[nf][1], AC1, -AC2));
      uint32_t a1 = packbf2(fmaf(S[nf][2], AC1, -AC2), fmaf(S[nf][3], AC1, -AC2));
      P[nf][0] = ex2_bf2(a0);
      P[nf][1] = ex2_bf2(a1);
      float2 q0 = unpk(P[nf][0]), q1 = unpk(P[nf][1]);
      l0r += q0.x + q0.y; l1r += q1.x + q1.y;
    }
    #pragma unroll
    for (int kj=0; kj<4; ++kj){
      uint32_t ap[4] = { P[2*kj][0], P[2*kj][1], P[2*kj+1][0], P[2*kj+1][1] };
      #pragma unroll
      for (int nj=0; nj<4; ++nj){
        uint32_t bf[4];
        const __nv_bfloat16* p = &Vs[(nj*16 + ((lane>>4)<<3) + (lane&7))*72
                                     + kj*16 + (((lane>>3)&1)<<3)];
        ldsm4(bf[0],bf[1],bf[2],bf[3], smem_u32(p));
        mma16816(O[2*nj],   ap, &bf[0]);
        mma16816(O[2*nj+1], ap, &bf[2]);
      }
    }
  }
  l0r += __shfl_xor_sync(0xffffffffu,l0r,1); l0r += __shfl_xor_sync(0xffffffffu,l0r,2);
  l1r += __shfl_xor_sync(0xffffffffu,l1r,1); l1r += __shfl_xor_sync(0xffffffffu,l1r,2);
  float il0 = 1.f/l0r, il1 = 1.f/l1r;
  int hh = bh & 15, b = bh >> 4;
  int r0 = b*KSEL + qt*128 + w*16 + (lane>>2);
  #pragma unroll
  for (int nf=0;nf<8;++nf){
    int col = hh*64 + nf*8 + (lane&3)*2;
    *(uint32_t*)&g_o[(size_t)r0*DIM + col]     = packbf2(O[nf][0]*il0, O[nf][1]*il0);
    *(uint32_t*)&g_o[(size_t)(r0+8)*DIM + col] = packbf2(O[nf][2]*il1, O[nf][3]*il1);
  }
}

// ---------------- launch ----------------
extern "C" void kernel_launch(void* const* d_in, const int* in_sizes, int n_in,
                              void* d_out, int out_size){
  const float* x    = (const float*)d_in[0];
  const float* rw   = (const float*)d_in[1];
  const float* ln1g = (const float*)d_in[2];
  const float* ln1b = (const float*)d_in[3];
  const float* ln2g = (const float*)d_in[4];
  const float* ln2b = (const float*)d_in[5];
  const float* wqkv = (const float*)d_in[6];
  const float* wo   = (const float*)d_in[7];
  const float* w1   = (const float*)d_in[8];
  const float* w2   = (const float*)d_in[9];
  float* out = (float*)d_out;

  static cudaStream_t s2 = nullptr, s3 = nullptr;
  static cudaEvent_t evF = nullptr, evT = nullptr, evM = nullptr;
  static bool attr_set = false;
  if (!attr_set){
    cudaFuncSetAttribute(gemm_kernel<0>, cudaFuncAttributeMaxDynamicSharedMemorySize, GSMEM_TOTAL);
    cudaFuncSetAttribute(gemm_kernel<1>, cudaFuncAttributeMaxDynamicSharedMemorySize, GSMEM_TOTAL);
    cudaFuncSetAttribute(gemm_kernel<2>, cudaFuncAttributeMaxDynamicSharedMemorySize, GSMEM_TOTAL);
    cudaFuncSetAttribute(gemm_kernel<3>, cudaFuncAttributeMaxDynamicSharedMemorySize, GSMEM_TOTAL);
    cudaFuncSetAttribute(attn_kernel,    cudaFuncAttributeMaxDynamicSharedMemorySize, ASMEM_TOTAL);
    cudaStreamCreateWithFlags(&s2, cudaStreamNonBlocking);
    cudaStreamCreateWithFlags(&s3, cudaStreamNonBlocking);
    cudaEventCreateWithFlags(&evF, cudaEventDisableTiming);
    cudaEventCreateWithFlags(&evT, cudaEventDisableTiming);
    cudaEventCreateWithFlags(&evM, cudaEventDisableTiming);
    attr_set = true;
  }

  // fork: transposes on s2, out-copy on s3, router chain on the main stream
  cudaEventRecord(evF, 0);
  cudaStreamWaitEvent(s2, evF, 0);
  cudaStreamWaitEvent(s3, evF, 0);
  transpose_all<<<12288, dim3(32,8), 0, s2>>>(wqkv, wo, w1, w2);
  cudaEventRecord(evT, s2);
  cudaMemcpyAsync(out, x, (size_t)BATCH*SEQ*DIM*sizeof(float), cudaMemcpyDeviceToDevice, s3);
  cudaEventRecord(evM, s3);

  logits_kernel<<<BATCH*SEQ/8, 256>>>(x, rw);
  topk_kernel<<<BATCH, 1024>>>();
  ln_kernel<<<MTOT, 256>>>(x, ln1g, ln1b, 0);
  cudaStreamWaitEvent(0, evT, 0);     // weights ready
  gemm_kernel<0><<<dim3(3*DIM/GBN, MTOT/GBM), 256, GSMEM_TOTAL>>>(nullptr);
  attn_kernel<<<dim3(KSEL/128, BATCH*NH), 256, ASMEM_TOTAL>>>();
  gemm_kernel<1><<<dim3(DIM/GBN,   MTOT/GBM), 256, GSMEM_TOTAL>>>(nullptr);
  ln_kernel<<<MTOT, 256>>>(x, ln2g, ln2b, 1);
  gemm_kernel<2><<<dim3(DFF/GBN,   MTOT/GBM), 256, GSMEM_TOTAL>>>(nullptr);
  cudaStreamWaitEvent(0, evM, 0);     // out pre-copy done
  gemm_kernel<3><<<dim3(DIM/GBN,   MTOT/GBM), 256, GSMEM_TOTAL>>>(out);
}